// round 7
// baseline (speedup 1.0000x reference)
#include <cuda_runtime.h>
#include <math.h>
#include <stdint.h>

// Problem constants (fixed by the reference)
#define N_NODES 50000
#define N_EDGES 800000
#define IN_DIM  128
#define H_DIM   128
#define OUT_DIM 64
#define H1_DIM  512
#define BC_N    640                               // [w1 | l0w] fused width
#define EW_BLOCKS ((N_EDGES * 16 + 255) / 256)   // 50000
#define SCAN_NB ((N_NODES + 511) / 512)          // 98

// alpha = 0.0 in reference -> x0/conv_w2 terms vanish.
#define BETA0 0.6931471805599453f   /* ln(2)   */
#define BETA1 0.4054651081081644f   /* ln(1.5) */

// ---------------- device scratch (static globals; no cudaMalloc allowed) ----
__device__ float  g_xt[N_NODES * IN_DIM];     // tf32-rounded x
__device__ float  g_bc640[IN_DIM * BC_N];     // [w1 | l0w] tf32-rounded
__device__ float  g_bb640[BC_N];              // [b1 | l0b]
__device__ float  g_w2t[512 * OUT_DIM];
__device__ float  g_l1wt[H_DIM * OUT_DIM];
__device__ float  g_cw1t[2 * H_DIM * H_DIM];
__device__ float  g_h1[N_NODES * H1_DIM];
__device__ float  g_h2[N_NODES * OUT_DIM];
__device__ float  g_glp[N_NODES * 128];   // [logits | lp] per row
__device__ float  g_P[OUT_DIM * OUT_DIM];
__device__ float  g_Wcat[OUT_DIM * 128];  // [w3 | w3@P], tf32-rounded
__device__ float  g_bcat[128];            // [b3 | b3@P]
__device__ float  g_hA[N_NODES * H_DIM];
__device__ float  g_hB[N_NODES * H_DIM];
__device__ float  g_agg[N_NODES * H_DIM];
__device__ float  g_ewraw[N_EDGES];
__device__ float  g_ewp[N_EDGES];
__device__ float  g_normw[N_EDGES];
__device__ int    g_esrc[N_EDGES];
__device__ int    g_cnt[N_NODES];
__device__ int    g_cursor[N_NODES];
__device__ int    g_rowptr[N_NODES + 1];
__device__ int    g_bsum[SCAN_NB + 1];
__device__ double g_psum[EW_BLOCKS];
__device__ double g_psum2[EW_BLOCKS];
__device__ float  g_stats[2];
__device__ float  g_dinv[N_NODES];

// ---------------- tf32 helpers ----------------------------------------------
__device__ __forceinline__ uint32_t f2tf32(float f)
{
    uint32_t o;
    asm("cvt.rna.tf32.f32 %0, %1;" : "=r"(o) : "f"(f));
    return o;
}
__device__ __forceinline__ float tf32r(float f) { return __uint_as_float(f2tf32(f)); }

__device__ __forceinline__ void mma_tf32(float d[4], const uint32_t a[4], const uint32_t b[2])
{
    asm volatile(
        "mma.sync.aligned.m16n8k8.row.col.f32.tf32.tf32.f32 "
        "{%0,%1,%2,%3}, {%4,%5,%6,%7}, {%8,%9}, {%0,%1,%2,%3};"
        : "+f"(d[0]), "+f"(d[1]), "+f"(d[2]), "+f"(d[3])
        : "r"(a[0]), "r"(a[1]), "r"(a[2]), "r"(a[3]), "r"(b[0]), "r"(b[1]));
}

__device__ __forceinline__ void cpa16(uint32_t dst, const float* src, uint32_t sz)
{
    asm volatile("cp.async.cg.shared.global [%0], [%1], 16, %2;"
                 :: "r"(dst), "l"(src), "r"(sz));
}
__device__ __forceinline__ void cpa_commit() { asm volatile("cp.async.commit_group;"); }
__device__ __forceinline__ void cpa_wait2()  { asm volatile("cp.async.wait_group 2;"); }

// ---------------- tf32 tensor-core GEMM (cp.async 4-stage) ------------------
// C = relu?( alpha*(A@B) + bias + addA*A ) [+ tf32 rounding of output]
// Split epilogue: columns [0,nsplit) -> C1 (ld nsplit), [nsplit,N) -> C2.
// A, B must already be tf32-rounded fp32.
// TNQ=1: BN=64,  3 CTAs/SM;  TNQ=2: BN=128, 2 CTAs/SM.
// smem: A [m][k] stride 20, B [k][n] stride BN+8 (conflict-free frag loads).

#define SKA 20
#define A_WORDS (128 * SKA)   // 2560
#define NSTAGE 4

template<int TNQ>
__global__ __launch_bounds__(256, 4 - TNQ)
void gemm_tc(const float* __restrict__ A, const float* __restrict__ B,
             const float* __restrict__ bias,
             float* __restrict__ C1, float* __restrict__ C2, int nsplit,
             int M, int N, int K, float alpha, float addA, int do_relu, int round_out)
{
    constexpr int BN  = 64 * TNQ;
    constexpr int SKB = BN + 8;
    constexpr int B_WORDS = 16 * SKB;
    extern __shared__ float smem[];
    float* As = smem;
    float* Bs = smem + NSTAGE * A_WORDS;

    const int tid  = threadIdx.x;
    const int lane = tid & 31;
    const int wid  = tid >> 5;
    const int wm   = wid & 3;
    const int wn   = wid >> 2;
    const int gid  = lane >> 2;
    const int tig  = lane & 3;
    const int m0   = blockIdx.x * 128;
    const int n0   = blockIdx.y * BN;

    // staging roles
    const int am     = tid >> 1;            // A row 0..127
    const int akq    = (tid & 1) * 2;       // chunks akq, akq+1
    const uint32_t asz = ((m0 + am) < M) ? 16u : 0u;
    const float* Apt = A + (size_t)(m0 + am) * K + akq * 4;
    const int bk     = tid >> 4;            // B k-row 0..15
    const int bnq    = (tid & 15) * 4 * TNQ;
    const float* Bpt = B + (size_t)bk * N + n0 + bnq;

    uint32_t as_base = (uint32_t)__cvta_generic_to_shared(As);
    uint32_t bs_base = (uint32_t)__cvta_generic_to_shared(Bs);
    const uint32_t adst0 = as_base + (am * SKA + akq * 4) * 4;
    const uint32_t bdst0 = bs_base + (bk * SKB + bnq) * 4;

    float d[2][4 * TNQ][4];
#pragma unroll
    for (int f = 0; f < 2; f++)
#pragma unroll
        for (int g = 0; g < 4 * TNQ; g++)
#pragma unroll
            for (int i = 0; i < 4; i++) d[f][g][i] = 0.f;

    const int ntiles = K >> 4;   // K >= 64 always -> ntiles >= 4

    // prefetch tiles 0..2
#pragma unroll
    for (int t = 0; t < 3; t++) {
        const uint32_t ad = adst0 + t * (A_WORDS * 4);
        const uint32_t bd = bdst0 + t * (B_WORDS * 4);
        cpa16(ad, Apt + t * 16, asz);
        cpa16(ad + 16, Apt + t * 16 + 4, asz);
#pragma unroll
        for (int q = 0; q < TNQ; q++)
            cpa16(bd + q * 16, Bpt + (size_t)t * 16 * N + q * 4, 16);
        cpa_commit();
    }

    for (int t = 0; t < ntiles; t++) {
        cpa_wait2();            // oldest outstanding (tile t) complete
        __syncthreads();

        // compute tile t from slot t&3
        const int s = t & 3;
        const float* Ab = As + s * A_WORDS;
        const float* Bb = Bs + s * B_WORDS;
#pragma unroll
        for (int ks = 0; ks < 16; ks += 8) {
            uint32_t af[2][4];
#pragma unroll
            for (int f = 0; f < 2; f++) {
                const int rb = wm * 32 + f * 16 + gid;
                af[f][0] = __float_as_uint(Ab[rb * SKA + ks + tig]);
                af[f][1] = __float_as_uint(Ab[(rb + 8) * SKA + ks + tig]);
                af[f][2] = __float_as_uint(Ab[rb * SKA + ks + tig + 4]);
                af[f][3] = __float_as_uint(Ab[(rb + 8) * SKA + ks + tig + 4]);
            }
            uint32_t bf[4 * TNQ][2];
#pragma unroll
            for (int g = 0; g < 4 * TNQ; g++) {
                const int nb = wn * 32 * TNQ + g * 8 + gid;
                bf[g][0] = __float_as_uint(Bb[(ks + tig) * SKB + nb]);
                bf[g][1] = __float_as_uint(Bb[(ks + tig + 4) * SKB + nb]);
            }
#pragma unroll
            for (int f = 0; f < 2; f++)
#pragma unroll
                for (int g = 0; g < 4 * TNQ; g++)
                    mma_tf32(d[f][g], af[f], bf[g]);
        }

        // issue tile t+3 into slot (t+3)&3 (same smem as tile t-1, already free)
        const int tp = t + 3;
        if (tp < ntiles) {
            const int sl = tp & 3;
            const uint32_t ad = adst0 + sl * (A_WORDS * 4);
            const uint32_t bd = bdst0 + sl * (B_WORDS * 4);
            cpa16(ad, Apt + tp * 16, asz);
            cpa16(ad + 16, Apt + tp * 16 + 4, asz);
#pragma unroll
            for (int q = 0; q < TNQ; q++)
                cpa16(bd + q * 16, Bpt + (size_t)tp * 16 * N + q * 4, 16);
        }
        cpa_commit();
    }

    // epilogue (split write)
#pragma unroll
    for (int f = 0; f < 2; f++) {
        const int r0 = m0 + wm * 32 + f * 16 + gid;
#pragma unroll
        for (int g = 0; g < 4 * TNQ; g++) {
            const int cc = n0 + wn * 32 * TNQ + g * 8 + 2 * tig;
#pragma unroll
            for (int h = 0; h < 2; h++) {
                const int gm = r0 + h * 8;
                if (gm >= M) continue;
                float v0 = alpha * d[f][g][2 * h + 0];
                float v1 = alpha * d[f][g][2 * h + 1];
                if (bias) {
                    float2 bb = *(const float2*)&bias[cc];
                    v0 += bb.x; v1 += bb.y;
                }
                if (addA != 0.f) {  // residual path: N == K, no split
                    float2 r = *(const float2*)&A[(size_t)gm * K + cc];
                    v0 += addA * r.x; v1 += addA * r.y;
                }
                if (do_relu) { v0 = fmaxf(v0, 0.f); v1 = fmaxf(v1, 0.f); }
                if (round_out) { v0 = tf32r(v0); v1 = tf32r(v1); }
                if (cc < nsplit)
                    *(float2*)&C1[(size_t)gm * nsplit + cc] = make_float2(v0, v1);
                else
                    *(float2*)&C2[(size_t)gm * (N - nsplit) + (cc - nsplit)] = make_float2(v0, v1);
            }
        }
    }
}

// ---------------- fused tf32 rounding / operand packing ---------------------
#define RT_N0 (N_NODES * IN_DIM)                 // x
#define RT_N1 (RT_N0 + IN_DIM * 512)             // w1  -> bc640[:,0:512]
#define RT_N2 (RT_N1 + IN_DIM * H_DIM)           // l0w -> bc640[:,512:640]
#define RT_N3 (RT_N2 + 512 * OUT_DIM)            // w2
#define RT_N4 (RT_N3 + H_DIM * OUT_DIM)          // l1w
#define RT_N5 (RT_N4 + 2 * H_DIM * H_DIM)        // cw1
#define RT_N6 (RT_N5 + 512)                      // b1  -> bb640[0:512]
#define RT_N7 (RT_N6 + H_DIM)                    // l0b -> bb640[512:640]
__global__ void rtall_kernel(const float* __restrict__ x, const float* __restrict__ w1,
                             const float* __restrict__ l0w, const float* __restrict__ w2,
                             const float* __restrict__ l1w, const float* __restrict__ cw1,
                             const float* __restrict__ b1, const float* __restrict__ l0b)
{
    int i = blockIdx.x * 256 + threadIdx.x;
    if (i < RT_N0)      g_xt[i] = tf32r(x[i]);
    else if (i < RT_N1) {
        int j = i - RT_N0;                     // k*512 + n
        g_bc640[(j >> 9) * BC_N + (j & 511)] = tf32r(w1[j]);
    } else if (i < RT_N2) {
        int j = i - RT_N1;                     // k*128 + n
        g_bc640[(j >> 7) * BC_N + 512 + (j & 127)] = tf32r(l0w[j]);
    }
    else if (i < RT_N3) g_w2t[i - RT_N2] = tf32r(w2[i - RT_N2]);
    else if (i < RT_N4) g_l1wt[i - RT_N3] = tf32r(l1w[i - RT_N3]);
    else if (i < RT_N5) g_cw1t[i - RT_N4] = tf32r(cw1[i - RT_N4]);
    else if (i < RT_N6) g_bb640[i - RT_N5] = b1[i - RT_N5];
    else if (i < RT_N7) g_bb640[512 + (i - RT_N6)] = l0b[i - RT_N6];
}

// ---------------- P = relu(SCALE * parsing[0]) ----------------
__global__ void p_kernel(const float* __restrict__ parsing)
{
    int i = blockIdx.x * blockDim.x + threadIdx.x;
    if (i < OUT_DIM * OUT_DIM) g_P[i] = fmaxf(2.0f * parsing[i], 0.0f);
}

// ---------------- Wcat = [w3 | w3@P], bcat = [b3 | b3@P] (tf32-rounded W) ---
__global__ void wcat_kernel(const float* __restrict__ w3, const float* __restrict__ b3)
{
    int idx = blockIdx.x * 256 + threadIdx.x;
    if (idx < 64 * 64) {
        int k = idx >> 6, j = idx & 63;
        g_Wcat[k * 128 + j] = tf32r(w3[k * 64 + j]);
        float s = 0.f;
        for (int i = 0; i < 64; i++) s += w3[k * 64 + i] * g_P[i * 64 + j];
        g_Wcat[k * 128 + 64 + j] = tf32r(s);
    } else if (idx < 64 * 64 + 64) {
        int j = idx - 64 * 64;
        g_bcat[j] = b3[j];
        float s = 0.f;
        for (int i = 0; i < 64; i++) s += b3[i] * g_P[i * 64 + j];
        g_bcat[64 + j] = s;
    }
}

// -------- edge weights + in-degree count (fused): ew, partial stats, cnt ----
__global__ void ew_kernel(const int* __restrict__ erow, const int* __restrict__ ecol)
{
    int t = blockIdx.x * 256 + threadIdx.x;
    int e = t >> 4;
    int l = t & 15;
    float v = 0.f;
    int c = -1;
    if (e < N_EDGES) {
        int r = erow[e];
        c = ecol[e];
        float4 a = *(const float4*)(g_glp + (size_t)r * 128 + l * 4);
        float4 b = *(const float4*)(g_glp + (size_t)c * 128 + 64 + l * 4);
        v = a.x * b.x + a.y * b.y + a.z * b.z + a.w * b.w;
    }
#pragma unroll
    for (int off = 8; off > 0; off >>= 1)
        v += __shfl_xor_sync(0xffffffffu, v, off);
    if (l == 0 && e < N_EDGES) {
        g_ewraw[e] = v;
        atomicAdd(&g_cnt[c], 1);
    }

    double s  = (l == 0 && e < N_EDGES) ? (double)v : 0.0;
    double s2 = (l == 0 && e < N_EDGES) ? (double)v * (double)v : 0.0;
    __shared__ double sh1[256];
    __shared__ double sh2[256];
    sh1[threadIdx.x] = s; sh2[threadIdx.x] = s2;
    __syncthreads();
    for (int off = 128; off > 0; off >>= 1) {
        if (threadIdx.x < off) {
            sh1[threadIdx.x] += sh1[threadIdx.x + off];
            sh2[threadIdx.x] += sh2[threadIdx.x + off];
        }
        __syncthreads();
    }
    if (threadIdx.x == 0) { g_psum[blockIdx.x] = sh1[0]; g_psum2[blockIdx.x] = sh2[0]; }
}

__global__ void stats_kernel()
{
    int t = threadIdx.x;
    double s = 0.0, s2 = 0.0;
    for (int i = t; i < EW_BLOCKS; i += 1024) { s += g_psum[i]; s2 += g_psum2[i]; }
    __shared__ double sh1[1024];
    __shared__ double sh2[1024];
    sh1[t] = s; sh2[t] = s2;
    __syncthreads();
    for (int off = 512; off > 0; off >>= 1) {
        if (t < off) { sh1[t] += sh1[t + off]; sh2[t] += sh2[t + off]; }
        __syncthreads();
    }
    if (t == 0) {
        double sum = sh1[0], sumsq = sh2[0];
        double mean = sum / (double)N_EDGES;
        double var = (sumsq - sum * sum / (double)N_EDGES) / (double)(N_EDGES - 1);
        g_stats[0] = (float)mean;
        g_stats[1] = (float)sqrt(1e-4 / var);
    }
}

// ---------------- parallel 3-phase scan of g_cnt -> g_rowptr, g_cursor ------
__global__ void scanA_kernel()
{
    __shared__ int sh[512];
    int b = blockIdx.x, t = threadIdx.x;
    int i = b * 512 + t;
    int v = (i < N_NODES) ? g_cnt[i] : 0;
    sh[t] = v;
    __syncthreads();
    for (int off = 1; off < 512; off <<= 1) {
        int add = (t >= off) ? sh[t - off] : 0;
        __syncthreads();
        sh[t] += add;
        __syncthreads();
    }
    if (i < N_NODES) g_rowptr[i + 1] = sh[t];   // block-local inclusive
    if (t == 511) g_bsum[b] = sh[511];
}

__global__ void scanB_kernel()
{
    __shared__ int sh[SCAN_NB];
    int t = threadIdx.x;
    if (t < SCAN_NB) sh[t] = g_bsum[t];
    __syncthreads();
    if (t == 0) {
        int run = 0;
        for (int b = 0; b < SCAN_NB; b++) { int x = sh[b]; sh[b] = run; run += x; }
    }
    __syncthreads();
    if (t < SCAN_NB) g_bsum[t] = sh[t];         // exclusive block offsets
}

__global__ void scanC_kernel()
{
    int b = blockIdx.x, t = threadIdx.x;
    int i = b * 512 + t;
    if (i < N_NODES) {
        int incl = g_rowptr[i + 1] + g_bsum[b];
        g_rowptr[i + 1] = incl;
        g_cursor[i] = incl - g_cnt[i];
        if (i == 0) g_rowptr[0] = 0;
    }
}

__global__ void scatter_kernel(const int* __restrict__ erow, const int* __restrict__ ecol)
{
    int e = blockIdx.x * blockDim.x + threadIdx.x;
    if (e < N_EDGES) {
        int p = atomicAdd(&g_cursor[ecol[e]], 1);
        g_esrc[p] = erow[e];
        g_ewp[p] = g_ewraw[e];
    }
}

__global__ void deg_kernel()
{
    int warp = (blockIdx.x * blockDim.x + threadIdx.x) >> 5;
    int lane = threadIdx.x & 31;
    if (warp >= N_NODES) return;
    float mean = g_stats[0], scale = g_stats[1];
    int s0 = g_rowptr[warp], s1 = g_rowptr[warp + 1];
    float s = 0.f;
    for (int p = s0 + lane; p < s1; p += 32) {
        float w = (g_ewp[p] - mean) * scale + 1.0f;
        g_ewp[p] = w;
        s += w;
    }
#pragma unroll
    for (int off = 16; off > 0; off >>= 1)
        s += __shfl_xor_sync(0xffffffffu, s, off);
    if (lane == 0) {
        float deg = s + 1.0f;
        g_dinv[warp] = (deg > 0.f) ? rsqrtf(deg) : 0.f;
    }
}

__global__ void normw_kernel()
{
    int warp = (blockIdx.x * blockDim.x + threadIdx.x) >> 5;
    int lane = threadIdx.x & 31;
    if (warp >= N_NODES) return;
    float di = g_dinv[warp];
    int s0 = g_rowptr[warp], s1 = g_rowptr[warp + 1];
    for (int p = s0 + lane; p < s1; p += 32)
        g_normw[p] = g_dinv[g_esrc[p]] * g_ewp[p] * di;
}

// ---- SpMM: agg[n] = tf32round( sum_in normw*h[src] + dinv[n]^2 * h[n] ) ----
// 4-way edge unroll for memory-level parallelism on the L2 gather chain.
__global__ void spmm_kernel(const float* __restrict__ hin, float* __restrict__ agg)
{
    int warp = (blockIdx.x * blockDim.x + threadIdx.x) >> 5;
    int lane = threadIdx.x & 31;
    if (warp >= N_NODES) return;
    const float4* h4 = (const float4*)hin;
    float di = g_dinv[warp];
    float selfw = di * di;
    float4 hv = h4[(size_t)warp * 32 + lane];
    float4 acc;
    acc.x = selfw * hv.x; acc.y = selfw * hv.y; acc.z = selfw * hv.z; acc.w = selfw * hv.w;
    int p = g_rowptr[warp];
    const int s1 = g_rowptr[warp + 1];
    for (; p + 4 <= s1; p += 4) {
        float w0 = g_normw[p],     w1 = g_normw[p + 1];
        float w2 = g_normw[p + 2], w3 = g_normw[p + 3];
        int i0 = g_esrc[p],     i1 = g_esrc[p + 1];
        int i2 = g_esrc[p + 2], i3 = g_esrc[p + 3];
        float4 v0 = h4[(size_t)i0 * 32 + lane];
        float4 v1 = h4[(size_t)i1 * 32 + lane];
        float4 v2 = h4[(size_t)i2 * 32 + lane];
        float4 v3 = h4[(size_t)i3 * 32 + lane];
        acc.x += w0 * v0.x + w1 * v1.x + w2 * v2.x + w3 * v3.x;
        acc.y += w0 * v0.y + w1 * v1.y + w2 * v2.y + w3 * v3.y;
        acc.z += w0 * v0.z + w1 * v1.z + w2 * v2.z + w3 * v3.z;
        acc.w += w0 * v0.w + w1 * v1.w + w2 * v2.w + w3 * v3.w;
    }
    for (; p < s1; p++) {
        float w = g_normw[p];
        float4 v = h4[(size_t)g_esrc[p] * 32 + lane];
        acc.x += w * v.x; acc.y += w * v.y; acc.z += w * v.z; acc.w += w * v.w;
    }
    acc.x = tf32r(acc.x); acc.y = tf32r(acc.y);
    acc.z = tf32r(acc.z); acc.w = tf32r(acc.w);
    ((float4*)agg)[(size_t)warp * 32 + lane] = acc;
}

// ---------------- launch ----------------------------------------------------
extern "C" void kernel_launch(void* const* d_in, const int* in_sizes, int n_in,
                              void* d_out, int out_size)
{
    const float* x       = (const float*)d_in[0];
    const int*   eidx    = (const int*)d_in[1];
    const float* w1      = (const float*)d_in[2];
    const float* b1      = (const float*)d_in[3];
    const float* w2      = (const float*)d_in[4];
    const float* b2      = (const float*)d_in[5];
    const float* w3      = (const float*)d_in[6];
    const float* b3      = (const float*)d_in[7];
    const float* parsing = (const float*)d_in[8];
    const float* l0w     = (const float*)d_in[9];
    const float* l0b     = (const float*)d_in[10];
    const float* l1w     = (const float*)d_in[11];
    const float* l1b     = (const float*)d_in[12];
    const float* cw1     = (const float*)d_in[13];
    float* out = (float*)d_out;
    const int* erow = eidx;
    const int* ecol = eidx + N_EDGES;

    float *p_xt, *p_bc640, *p_bb640, *p_w2t, *p_l1wt, *p_cw1t;
    float *p_h1, *p_h2, *p_glp, *p_Wcat, *p_bcat, *p_hA, *p_hB, *p_agg;
    int *p_cnt;
    cudaGetSymbolAddress((void**)&p_xt, g_xt);
    cudaGetSymbolAddress((void**)&p_bc640, g_bc640);
    cudaGetSymbolAddress((void**)&p_bb640, g_bb640);
    cudaGetSymbolAddress((void**)&p_w2t, g_w2t);
    cudaGetSymbolAddress((void**)&p_l1wt, g_l1wt);
    cudaGetSymbolAddress((void**)&p_cw1t, g_cw1t);
    cudaGetSymbolAddress((void**)&p_h1, g_h1);
    cudaGetSymbolAddress((void**)&p_h2, g_h2);
    cudaGetSymbolAddress((void**)&p_glp, g_glp);
    cudaGetSymbolAddress((void**)&p_Wcat, g_Wcat);
    cudaGetSymbolAddress((void**)&p_bcat, g_bcat);
    cudaGetSymbolAddress((void**)&p_hA, g_hA);
    cudaGetSymbolAddress((void**)&p_hB, g_hB);
    cudaGetSymbolAddress((void**)&p_agg, g_agg);
    cudaGetSymbolAddress((void**)&p_cnt, g_cnt);

    const int gmx = (N_NODES + 127) / 128;  // 391
    const int SM1 = NSTAGE * (A_WORDS + 16 * 72)  * 4;   // 59392 B, TNQ=1
    const int SM2 = NSTAGE * (A_WORDS + 16 * 136) * 4;   // 75776 B, TNQ=2
    cudaFuncSetAttribute(gemm_tc<1>, cudaFuncAttributeMaxDynamicSharedMemorySize, SM1);
    cudaFuncSetAttribute(gemm_tc<2>, cudaFuncAttributeMaxDynamicSharedMemorySize, SM2);

    // setup: tf32 rounding + operand packing, P, Wcat, zero counters
    rtall_kernel<<<(RT_N7 + 255) / 256, 256>>>(x, w1, l0w, w2, l1w, cw1, b1, l0b);
    p_kernel<<<4, 1024>>>(parsing);
    wcat_kernel<<<17, 256>>>(w3, b3);
    cudaMemsetAsync(p_cnt, 0, N_NODES * sizeof(int));

    // fused: [h1 | x0] = relu(x @ [w1 | l0w] + [b1 | l0b])
    gemm_tc<2><<<dim3(gmx, BC_N / 128), 256, SM2>>>(p_xt, p_bc640, p_bb640,
                                                    p_h1, p_hA, 512,
                                                    N_NODES, BC_N, IN_DIM, 1.f, 0.f, 1, 1);
    // h2 = relu(h1 @ w2 + b2)
    gemm_tc<1><<<dim3(gmx, 1), 256, SM1>>>(p_h1, p_w2t, b2, p_h2, nullptr, OUT_DIM,
                                           N_NODES, OUT_DIM, H1_DIM, 1.f, 0.f, 1, 1);
    // [logits | lp] = h2 @ Wcat + bcat
    gemm_tc<2><<<dim3(gmx, 1), 256, SM2>>>(p_h2, p_Wcat, p_bcat, p_glp, nullptr, 128,
                                           N_NODES, 128, OUT_DIM, 1.f, 0.f, 0, 0);

    // edge weights + per-node counts + stats
    ew_kernel<<<EW_BLOCKS, 256>>>(erow, ecol);
    stats_kernel<<<1, 1024>>>();

    // CSR build (parallel scan)
    scanA_kernel<<<SCAN_NB, 512>>>();
    scanB_kernel<<<1, 128>>>();
    scanC_kernel<<<SCAN_NB, 512>>>();
    scatter_kernel<<<(N_EDGES + 255) / 256, 256>>>(erow, ecol);
    deg_kernel<<<(N_NODES + 7) / 8, 256>>>();
    normw_kernel<<<(N_NODES + 7) / 8, 256>>>();

    // layer 0
    spmm_kernel<<<(N_NODES + 7) / 8, 256>>>(p_hA, p_agg);
    gemm_tc<2><<<dim3(gmx, 1), 256, SM2>>>(p_agg, p_cw1t, nullptr, p_hB, nullptr, H_DIM,
                                           N_NODES, H_DIM, H_DIM, BETA0, 1.f - BETA0, 1, 1);
    // layer 1
    spmm_kernel<<<(N_NODES + 7) / 8, 256>>>(p_hB, p_agg);
    gemm_tc<2><<<dim3(gmx, 1), 256, SM2>>>(p_agg, p_cw1t + H_DIM * H_DIM, nullptr, p_hA, nullptr, H_DIM,
                                           N_NODES, H_DIM, H_DIM, BETA1, 1.f - BETA1, 1, 1);
    // output
    gemm_tc<1><<<dim3(gmx, 1), 256, SM1>>>(p_hA, p_l1wt, l1b, out, nullptr, OUT_DIM,
                                           N_NODES, OUT_DIM, H_DIM, 1.f, 0.f, 0, 0);
}